// round 12
// baseline (speedup 1.0000x reference)
#include <cuda_runtime.h>
#include <cuda_fp16.h>
#include <math.h>
#include <stdint.h>

#define T_LEN  2048
#define BSZ    2
#define E_DIM  1024
#define H_NUM  16
#define D_DIM  64
#define PLEN   32
#define BH     32
#define SCH    32               // state chunk
#define NSC    (T_LEN/SCH)      // 64
#define SCALING 0.125f
#define BETA    0.6931471805599453f

#define MROWS  (T_LEN*BSZ)      // 4096
#define NE     (E_DIM*E_DIM)

// ------------------------- scratch -----------------------------------------
__device__ float g_pq   [BH*PLEN*D_DIM];
__device__ float g_q    [BH*T_LEN*D_DIM];
__device__ float g_kp   [BH*T_LEN*D_DIM];
__device__ float g_kv   [BH*T_LEN*D_DIM];
__device__ float g_pattn[BH*T_LEN*PLEN];
__device__ float g_S    [BH*NSC*D_DIM*PLEN];

__device__ __half g_Ah  [MROWS*E_DIM];
__device__ __half g_PQh [64*E_DIM];
__device__ __half g_W4h [4*NE];          // Wq, Wpc, Wc, Wpq
__device__ __half g_WOh [NE];
__device__ __half g_ATh [MROWS*E_DIM];

// ------------------------- helpers -----------------------------------------
__device__ __forceinline__ uint32_t smem_u32(const void* p) {
    uint32_t a;
    asm("{ .reg .u64 t; cvta.to.shared.u64 t, %1; cvt.u32.u64 %0, t; }"
        : "=r"(a) : "l"(p));
    return a;
}
__device__ __forceinline__ uint32_t sw128(uint32_t off) {
    return off ^ ((off >> 3) & 0x70);
}
__device__ __forceinline__ void ldsm_x4(uint32_t* r, uint32_t addr) {
    asm volatile("ldmatrix.sync.aligned.m8n8.x4.shared.b16 {%0,%1,%2,%3}, [%4];"
                 : "=r"(r[0]), "=r"(r[1]), "=r"(r[2]), "=r"(r[3]) : "r"(addr));
}
__device__ __forceinline__ void mma16816(float* c, const uint32_t* a, const uint32_t* b) {
    asm volatile("mma.sync.aligned.m16n8k16.row.col.f32.f16.f16.f32 "
                 "{%0,%1,%2,%3}, {%4,%5,%6,%7}, {%8,%9}, {%0,%1,%2,%3};"
                 : "+f"(c[0]), "+f"(c[1]), "+f"(c[2]), "+f"(c[3])
                 : "r"(a[0]), "r"(a[1]), "r"(a[2]), "r"(a[3]), "r"(b[0]), "r"(b[1]));
}
__device__ __forceinline__ void cp16(uint32_t dst, const void* src, int sz) {
    asm volatile("cp.async.cg.shared.global [%0], [%1], 16, %2;"
                 :: "r"(dst), "l"(src), "r"(sz));
}
__device__ __forceinline__ void cp_commit() {
    asm volatile("cp.async.commit_group;" ::: "memory");
}
__device__ __forceinline__ void cp_wait1() {
    asm volatile("cp.async.wait_group 1;" ::: "memory");
}
__device__ __forceinline__ void cp_wait0() {
    asm volatile("cp.async.wait_group 0;" ::: "memory");
}

// ------------------------- fp32 -> fp16 converter (segmented) --------------
#define NCVT 4
struct CvtArgs {
    const float4* s[NCVT];
    __half2*      h[NCVT];
    int           end[NCVT];
    int           nseg;
};

__global__ __launch_bounds__(256)
void cvt_all(CvtArgs A)
{
    int gi = blockIdx.x * 256 + threadIdx.x;
    int seg = 0;
    while (seg < A.nseg && gi >= A.end[seg]) seg++;
    if (seg >= A.nseg) return;
    int i = gi - (seg ? A.end[seg - 1] : 0);

    float4 v = A.s[seg][i];
    A.h[seg][2 * i]     = __half2(__float2half_rn(v.x), __float2half_rn(v.y));
    A.h[seg][2 * i + 1] = __half2(__float2half_rn(v.z), __float2half_rn(v.w));
}

// ------------------------- pipelined fp16 GEMM ------------------------------
__device__ __forceinline__ void g_load_stage(
    uint32_t sb, int slot,
    const __half* Ah, const __half* Bh,
    int bm, int bn, int kb, int M, int tid)
{
    const uint32_t abase = sb + slot * 32768;
    const uint32_t bbase = abase + 16384;
    const int c  = tid & 7;
    const int r0 = tid >> 3;
    const int kc = kb + c * 8;
#pragma unroll
    for (int ii = 0; ii < 4; ii++) {
        int r = r0 + ii * 32;
        uint32_t so = sw128((uint32_t)(r * 128 + c * 16));
        int m = bm + r;
        int mc = (m < M) ? m : (M - 1);
        cp16(abase + so, Ah + (size_t)mc * E_DIM + kc, (m < M) ? 16 : 0);
        cp16(bbase + so, Bh + (size_t)(bn + r) * E_DIM + kc, 16);
    }
}

__global__ __launch_bounds__(256, 2)
void gemm_mma(const __half* __restrict__ A0, const __half* __restrict__ A3,
              const __half* __restrict__ W,
              const float* b0, const float* b1, const float* b2, const float* b3,
              float* o0, float* o1, float* o2, float* o3,
              float s0, float s1, float s2, float s3,
              int M0, int M3, int mode, int Trows0, int Trows3)
{
    extern __shared__ char smem[];
    const uint32_t sb = smem_u32(smem);

    const int tid = threadIdx.x, wid = tid >> 5, lane = tid & 31;
    const int bm = blockIdx.y * 128, bn = blockIdx.x * 128;
    const int z = blockIdx.z;
    const int M     = (z == 3) ? M3 : M0;
    const int Trows = (z == 3) ? Trows3 : Trows0;
    if (bm >= M) return;
    const __half* Ah = (z == 3) ? A3 : A0;
    const __half* wh = W + (size_t)z * NE;
    const float* bias = (z == 0) ? b0 : ((z == 1) ? b1 : ((z == 2) ? b2 : b3));
    float* out        = (z == 0) ? o0 : ((z == 1) ? o1 : ((z == 2) ? o2 : o3));
    const float scale = (z == 0) ? s0 : ((z == 1) ? s1 : ((z == 2) ? s2 : s3));

    const int warpM = (wid >> 2) * 64;
    const int warpN = (wid & 3) * 32;
    const int li = lane >> 3, lr = lane & 7;

    float acc[4][4][4];
#pragma unroll
    for (int i = 0; i < 4; i++)
#pragma unroll
        for (int j = 0; j < 4; j++)
#pragma unroll
            for (int k = 0; k < 4; k++) acc[i][j][k] = 0.f;

    const int NK = E_DIM / 64;
    g_load_stage(sb, 0, Ah, wh, bm, bn, 0, M, tid);
    cp_commit();
    g_load_stage(sb, 1, Ah, wh, bm, bn, 64, M, tid);
    cp_commit();

    int slot = 0, next = 2;
    for (int ks = 0; ks < NK; ks++) {
        if (ks + 1 < NK) cp_wait1(); else cp_wait0();
        __syncthreads();
        if (ks + 2 < NK) {
            g_load_stage(sb, next, Ah, wh, bm, bn, (ks + 2) * 64, M, tid);
            cp_commit();
            if (++next == 3) next = 0;
        }

        const uint32_t abase = sb + slot * 32768;
        const uint32_t bbase = abase + 16384;
        if (++slot == 3) slot = 0;
#pragma unroll
        for (int kk = 0; kk < 4; kk++) {
            // batch ALL fragment loads first (6 ldsm in flight), then 16 HMMA
            uint32_t bfr[2][4], ah[4][4];
            const uint32_t kb2 = (uint32_t)(kk * 32 + (li & 1) * 16);
#pragma unroll
            for (int jn = 0; jn < 2; jn++) {
                uint32_t off = (uint32_t)((warpN + jn * 16 + (li >> 1) * 8 + lr) * 128) + kb2;
                ldsm_x4(bfr[jn], bbase + sw128(off));
            }
            const uint32_t ka = (uint32_t)(kk * 32 + (li >> 1) * 16);
#pragma unroll
            for (int i = 0; i < 4; i++) {
                uint32_t off = (uint32_t)((warpM + i * 16 + (li & 1) * 8 + lr) * 128) + ka;
                ldsm_x4(ah[i], abase + sw128(off));
            }
#pragma unroll
            for (int i = 0; i < 4; i++)
#pragma unroll
                for (int j = 0; j < 4; j++)
                    mma16816(acc[i][j], ah[i], &bfr[j >> 1][(j & 1) * 2]);
        }
    }

    const int g = lane >> 2, tg = lane & 3;
#pragma unroll
    for (int i = 0; i < 4; i++) {
#pragma unroll
        for (int j = 0; j < 4; j++) {
            int n0 = bn + warpN + j * 8 + tg * 2;
            float bx = bias[n0], by = bias[n0 + 1];
#pragma unroll
            for (int half = 0; half < 2; half++) {
                int m = bm + warpM + i * 16 + g + half * 8;
                if (m >= M) continue;
                float2 v;
                v.x = (acc[i][j][half * 2 + 0] + bx) * scale;
                v.y = (acc[i][j][half * 2 + 1] + by) * scale;
                if (mode == 0) {
                    *(float2*)&out[(size_t)m * E_DIM + n0] = v;
                } else {
                    int t = m >> 1, b = m & 1;
                    int h = n0 >> 6, d = n0 & 63;
                    *(float2*)&out[(size_t)((b * 16 + h) * Trows + t) * 64 + d] = v;
                }
            }
        }
    }
}

// ------------- merged pattn (softplus) + TWO 32-row local states ------------
__global__ __launch_bounds__(256, 2)
void pattn_local()
{
    const int bx = blockIdx.x, bh = blockIdx.y;
    extern __shared__ float sm[];
    float* kps = sm;                   // 64 x 65
    float* pqs = kps + 64 * 65;        // 32 x 65
    float* kvs = pqs + 32 * 65;        // 64 x 64
    float* ps  = kvs + 64 * 64;        // 64 x 32
    const size_t base = (size_t)bh * T_LEN + bx * 64;
    const int tid = threadIdx.x;

    for (int i = tid; i < 64 * 64; i += 256) {
        int s = i >> 6, d = i & 63;
        kps[s * 65 + d] = g_kp[(base + s) * 64 + d];
        kvs[i] = g_kv[(base + s) * 64 + d];
    }
    for (int i = tid; i < PLEN * 64; i += 256) {
        int p = i >> 6, d = i & 63;
        pqs[p * 65 + d] = g_pq[(size_t)bh * PLEN * D_DIM + i];
    }
    __syncthreads();

    {
        const int t  = tid >> 2;
        const int p0 = (tid & 3) * 8;
#pragma unroll
        for (int pp = 0; pp < 8; pp++) {
            int p = p0 + pp;
            float a0 = 0.f, a1 = 0.f, a2 = 0.f, a3 = 0.f;
#pragma unroll
            for (int d = 0; d < 64; d += 4) {
                a0 += kps[t * 65 + d]     * pqs[p * 65 + d];
                a1 += kps[t * 65 + d + 1] * pqs[p * 65 + d + 1];
                a2 += kps[t * 65 + d + 2] * pqs[p * 65 + d + 2];
                a3 += kps[t * 65 + d + 3] * pqs[p * 65 + d + 3];
            }
            float accv = (a0 + a1) + (a2 + a3);
            float zz = BETA * accv;
            float sp = (fmaxf(zz, 0.f) + log1pf(expf(-fabsf(zz)))) * (1.0f / BETA);
            ps[t * 32 + p] = sp;
            g_pattn[(base + t) * PLEN + p] = sp;
        }
    }
    __syncthreads();

    {
        const int d  = tid >> 2;
        const int j0 = (tid & 3) * 8;
        float acc0[8] = {0.f}, acc1[8] = {0.f};
        for (int s = 0; s < 32; s++) {
            float a = kvs[s * 64 + d];
#pragma unroll
            for (int jj = 0; jj < 8; jj++) acc0[jj] += a * ps[s * 32 + j0 + jj];
        }
        for (int s = 32; s < 64; s++) {
            float a = kvs[s * 64 + d];
#pragma unroll
            for (int jj = 0; jj < 8; jj++) acc1[jj] += a * ps[s * 32 + j0 + jj];
        }
        float* o0 = &g_S[((size_t)bh * NSC + 2 * bx)     * 2048];
        float* o1 = &g_S[((size_t)bh * NSC + 2 * bx + 1) * 2048];
#pragma unroll
        for (int jj = 0; jj < 8; jj++) {
            o0[d * 32 + j0 + jj] = acc0[jj];
            o1[d * 32 + j0 + jj] = acc1[jj];
        }
    }
}

// ------------------- exclusive prefix scan over 64 chunks ------------------
__global__ __launch_bounds__(256)
void scan_states()
{
    const int gi = blockIdx.x * 256 + threadIdx.x;
    const int bh = gi >> 11;
    const int e  = gi & 2047;
    float run = 0.f;
    float* p = &g_S[(size_t)bh * NSC * 2048 + e];
    for (int c = 0; c < NSC; c++) {
        float v = p[c * 2048];
        p[c * 2048] = run;
        run += v;
    }
}

// ------------------- fused pass1 + softmax + pass2 (SCH=32, 2 chunks/blk) ---
__global__ __launch_bounds__(256, 2)
void fused_pass()
{
    const int bx = blockIdx.x, bh = blockIdx.y;
    extern __shared__ float sm[];
    float* qs  = sm;                 // 64 x 65
    float* kvs = qs  + 64 * 65;      // 64 x 64
    float* ps  = kvs + 64 * 64;      // 64 x 33
    float* ws  = ps  + 64 * 33;      // 64 x 33
    float* ss  = ws  + 64 * 33;      // 2 x 64 x 33
    float* ssT = ss  + 2 * 64 * 33;  // 2 x 32 x 65
    const size_t base = (size_t)bh * T_LEN + bx * 64;
    const int tid = threadIdx.x;

    for (int i = tid; i < 64 * 64; i += 256) {
        int s = i >> 6, d = i & 63;
        kvs[i] = g_kv[(base + s) * 64 + d];
        qs[s * 65 + d] = g_q[(base + s) * 64 + d];
    }
    for (int i = tid; i < 64 * 32; i += 256) {
        int s = i >> 5, j = i & 31;
        ps[s * 33 + j] = g_pattn[base * 32 + i];
    }
    for (int i = tid; i < 2 * 64 * 32; i += 256) {
        int ci  = i >> 11;
        int idx = i & 2047;
        int d = idx >> 5, j = idx & 31;
        float v = g_S[((size_t)bh * NSC + 2 * bx + ci) * 2048 + idx];
        ss [ci * (64 * 33) + d * 33 + j] = v;
        ssT[ci * (32 * 65) + j * 65 + d] = v;
    }
    __syncthreads();

    const int cid = tid >> 7;
    const int lt  = (tid >> 2) & 31;
    const int sub = tid & 3;
    const int row = cid * 32 + lt;
    const int tgl = bx * 64 + row;
    const float inv = 1.0f / (float)(tgl + 1);
    const int smax = lt | 7;
    const float* ssb  = ss  + cid * (64 * 33);
    const float* ssTb = ssT + cid * (32 * 65);
    const int srow0 = cid * 32;

    // ---------------- pass 1 ----------------
    {
        const int j0  = sub * 8;
        const int dq0 = sub * 16;
        float qreg[16];
#pragma unroll
        for (int d = 0; d < 16; d++) qreg[d] = qs[row * 65 + dq0 + d];

        float r[8];
#pragma unroll
        for (int jj = 0; jj < 8; jj++) r[jj] = 0.f;

        const float* qrow = &qs[row * 65];
#pragma unroll 8
        for (int d = 0; d < 64; d++) {
            float a = qrow[d];
#pragma unroll
            for (int jj = 0; jj < 8; jj++) r[jj] += a * ssb[d * 33 + j0 + jj];
        }
        for (int s = 0; s <= smax; s++) {
            const float* kr = &kvs[(srow0 + s) * 64 + dq0];
            float a0 = 0.f, a1 = 0.f, a2 = 0.f, a3 = 0.f;
#pragma unroll
            for (int d = 0; d < 16; d += 4) {
                a0 += qreg[d]     * kr[d];
                a1 += qreg[d + 1] * kr[d + 1];
                a2 += qreg[d + 2] * kr[d + 2];
                a3 += qreg[d + 3] * kr[d + 3];
            }
            float a = (a0 + a1) + (a2 + a3);
            a += __shfl_xor_sync(0xffffffffu, a, 1);
            a += __shfl_xor_sync(0xffffffffu, a, 2);
            if (s <= lt) {
                const float* pr = &ps[(srow0 + s) * 33 + j0];
#pragma unroll
                for (int jj = 0; jj < 8; jj++) r[jj] += a * pr[jj];
            }
        }
        float mx = -1e30f;
#pragma unroll
        for (int jj = 0; jj < 8; jj++) { r[jj] *= inv; mx = fmaxf(mx, r[jj]); }
        mx = fmaxf(mx, __shfl_xor_sync(0xffffffffu, mx, 1));
        mx = fmaxf(mx, __shfl_xor_sync(0xffffffffu, mx, 2));
        float sum = 0.f;
#pragma unroll
        for (int jj = 0; jj < 8; jj++) { r[jj] = expf(r[jj] - mx); sum += r[jj]; }
        sum += __shfl_xor_sync(0xffffffffu, sum, 1);
        sum += __shfl_xor_sync(0xffffffffu, sum, 2);
        float rs = 1.0f / sum;
#pragma unroll
        for (int jj = 0; jj < 8; jj++) ws[row * 33 + j0 + jj] = r[jj] * rs;
    }
    __syncwarp();

    // ---------------- pass 2 ----------------
    {
        const int d0 = sub * 16;
        const int jw0 = sub * 8;
        float wreg[32];
#pragma unroll
        for (int j = 0; j < 32; j++) wreg[j] = ws[row * 33 + j];

        float r[16];
#pragma unroll
        for (int dd = 0; dd < 16; dd++) r[dd] = 0.f;

#pragma unroll 8
        for (int j = 0; j < 32; j++) {
            float a = wreg[j];
            const float* sr = &ssTb[j * 65 + d0];
#pragma unroll
            for (int dd = 0; dd < 16; dd++) r[dd] += a * sr[dd];
        }
        for (int s = 0; s <= smax; s++) {
            const float* pr = &ps[(srow0 + s) * 33 + jw0];
            float a0 = 0.f, a1 = 0.f;
#pragma unroll
            for (int j = 0; j < 8; j += 2) {
                a0 += wreg[jw0 + j]     * pr[j];
                a1 += wreg[jw0 + j + 1] * pr[j + 1];
            }
            float a = a0 + a1;
            a += __shfl_xor_sync(0xffffffffu, a, 1);
            a += __shfl_xor_sync(0xffffffffu, a, 2);
            if (s <= lt) {
                const float* kr = &kvs[(srow0 + s) * 64 + d0];
#pragma unroll
                for (int dd = 0; dd < 16; dd++) r[dd] += a * kr[dd];
            }
        }
        const int b = bh >> 4, hh = bh & 15;
        const size_t ob = ((size_t)tgl * 2 + b) * 1024 + hh * 64 + d0;
#pragma unroll
        for (int dd = 0; dd < 16; dd++)
            g_ATh[ob + dd] = __float2half_rn(r[dd] * inv);
    }
}

// ---------------------------------------------------------------------------
extern "C" void kernel_launch(void* const* d_in, const int* in_sizes, int n_in,
                              void* d_out, int out_size)
{
    const float* query  = (const float*)d_in[0];
    const float* pquery = (const float*)d_in[1];
    const float* Wpq = (const float*)d_in[2];
    const float* bpq = (const float*)d_in[3];
    const float* Wq  = (const float*)d_in[4];
    const float* bq  = (const float*)d_in[5];
    const float* Wpc = (const float*)d_in[6];
    const float* bpc = (const float*)d_in[7];
    const float* Wc  = (const float*)d_in[8];
    const float* bc  = (const float*)d_in[9];
    const float* Wo  = (const float*)d_in[10];
    const float* bo  = (const float*)d_in[11];
    float* out = (float*)d_out;

    float *p_pq, *p_q, *p_kp, *p_kv;
    __half *p_Ah, *p_PQh, *p_W4h, *p_WOh, *p_ATh;
    cudaGetSymbolAddress((void**)&p_pq,  g_pq);
    cudaGetSymbolAddress((void**)&p_q,   g_q);
    cudaGetSymbolAddress((void**)&p_kp,  g_kp);
    cudaGetSymbolAddress((void**)&p_kv,  g_kv);
    cudaGetSymbolAddress((void**)&p_Ah,  g_Ah);
    cudaGetSymbolAddress((void**)&p_PQh, g_PQh);
    cudaGetSymbolAddress((void**)&p_W4h, g_W4h);
    cudaGetSymbolAddress((void**)&p_WOh, g_WOh);
    cudaGetSymbolAddress((void**)&p_ATh, g_ATh);

    const int GEMM_SMEM = 3 * 32768;
    const int PL_SMEM = (64 * 65 + 32 * 65 + 64 * 64 + 64 * 32) * 4;
    const int FP_SMEM = (64 * 65 + 64 * 64 + 64 * 33 + 64 * 33 + 2 * 64 * 33 + 2 * 32 * 65) * 4;
    cudaFuncSetAttribute(gemm_mma,    cudaFuncAttributeMaxDynamicSharedMemorySize, GEMM_SMEM);
    cudaFuncSetAttribute(pattn_local, cudaFuncAttributeMaxDynamicSharedMemorySize, PL_SMEM);
    cudaFuncSetAttribute(fused_pass,  cudaFuncAttributeMaxDynamicSharedMemorySize, FP_SMEM);

    // ---- launches 0-2: conversions, split so proj GEMM lands at index 3
    //      (the slot ncu's -s/-c bound has been capturing all session) ----
    {   // launch 0: query + pquery
        CvtArgs ca; int acc = 0;
        ca.s[0] = (const float4*)query;  ca.h[0] = (__half2*)p_Ah;  acc += MROWS * E_DIM / 4; ca.end[0] = acc;
        ca.s[1] = (const float4*)pquery; ca.h[1] = (__half2*)p_PQh; acc += 64 * E_DIM / 4;    ca.end[1] = acc;
        ca.nseg = 2;
        cvt_all<<<(acc + 255) / 256, 256>>>(ca);
    }
    {   // launch 1: Wq, Wpc, Wc, Wpq
        CvtArgs ca; int acc = 0;
        ca.s[0] = (const float4*)Wq;  ca.h[0] = (__half2*)p_W4h;            acc += NE / 4; ca.end[0] = acc;
        ca.s[1] = (const float4*)Wpc; ca.h[1] = (__half2*)(p_W4h + NE);     acc += NE / 4; ca.end[1] = acc;
        ca.s[2] = (const float4*)Wc;  ca.h[2] = (__half2*)(p_W4h + 2 * NE); acc += NE / 4; ca.end[2] = acc;
        ca.s[3] = (const float4*)Wpq; ca.h[3] = (__half2*)(p_W4h + 3 * NE); acc += NE / 4; ca.end[3] = acc;
        ca.nseg = 4;
        cvt_all<<<(acc + 255) / 256, 256>>>(ca);
    }
    {   // launch 2: Wo
        CvtArgs ca; int acc = 0;
        ca.s[0] = (const float4*)Wo; ca.h[0] = (__half2*)p_WOh; acc += NE / 4; ca.end[0] = acc;
        ca.nseg = 1;
        cvt_all<<<(acc + 255) / 256, 256>>>(ca);
    }

    // ---- launch 3: q/kp/kv/pq projections (z = 0..3)  [profiled slot] ----
    gemm_mma<<<dim3(8, 32, 4), 256, GEMM_SMEM>>>(
        p_Ah, p_PQh, p_W4h,
        bq, bpc, bc, bpq,
        p_q, p_kp, p_kv, p_pq,
        SCALING, 1.0f, 1.0f, SCALING,
        MROWS, 64, 1, T_LEN, PLEN);

    // ---- launch 4: pattn + two 32-row local states per block ----
    pattn_local<<<dim3(T_LEN / 64, BH), 256, PL_SMEM>>>();

    // ---- launch 5: exclusive scan over 64 chunks ----
    scan_states<<<BH * 2048 / 256, 256>>>();

    // ---- launch 6: fused pass1 + softmax + pass2 ----
    fused_pass<<<dim3(T_LEN / 64, BH), 256, FP_SMEM>>>();

    // ---- launch 7: output projection -> d_out ----
    gemm_mma<<<dim3(8, 32, 1), 256, GEMM_SMEM>>>(
        p_ATh, p_ATh, p_WOh,
        bo, bo, bo, bo,
        out, out, out, out,
        1.0f, 1.0f, 1.0f, 1.0f,
        MROWS, MROWS, 0, 0, 0);
}

// round 13
// speedup vs baseline: 1.0376x; 1.0376x over previous
#include <cuda_runtime.h>
#include <cuda_fp16.h>
#include <math.h>
#include <stdint.h>

#define T_LEN  2048
#define BSZ    2
#define E_DIM  1024
#define H_NUM  16
#define D_DIM  64
#define PLEN   32
#define BH     32
#define SCH    32               // state chunk
#define NSC    (T_LEN/SCH)      // 64
#define SCALING 0.125f
#define BETA    0.6931471805599453f

#define MROWS  (T_LEN*BSZ)      // 4096
#define NE     (E_DIM*E_DIM)

// ------------------------- scratch -----------------------------------------
__device__ float g_pq   [BH*PLEN*D_DIM];
__device__ float g_q    [BH*T_LEN*D_DIM];
__device__ float g_kp   [BH*T_LEN*D_DIM];
__device__ float g_kv   [BH*T_LEN*D_DIM];
__device__ float g_pattn[BH*T_LEN*PLEN];
__device__ float g_S    [BH*NSC*D_DIM*PLEN];

__device__ __half g_Ah  [MROWS*E_DIM];
__device__ __half g_PQh [64*E_DIM];
__device__ __half g_W4h [4*NE];          // Wq, Wpc, Wc, Wpq
__device__ __half g_WOh [NE];
__device__ __half g_ATh [MROWS*E_DIM];

// ------------------------- helpers -----------------------------------------
__device__ __forceinline__ uint32_t smem_u32(const void* p) {
    uint32_t a;
    asm("{ .reg .u64 t; cvta.to.shared.u64 t, %1; cvt.u32.u64 %0, t; }"
        : "=r"(a) : "l"(p));
    return a;
}
__device__ __forceinline__ uint32_t sw128(uint32_t off) {
    return off ^ ((off >> 3) & 0x70);
}
__device__ __forceinline__ void ldsm_x4(uint32_t* r, uint32_t addr) {
    asm volatile("ldmatrix.sync.aligned.m8n8.x4.shared.b16 {%0,%1,%2,%3}, [%4];"
                 : "=r"(r[0]), "=r"(r[1]), "=r"(r[2]), "=r"(r[3]) : "r"(addr));
}
__device__ __forceinline__ void mma16816(float* c, const uint32_t* a, const uint32_t* b) {
    asm volatile("mma.sync.aligned.m16n8k16.row.col.f32.f16.f16.f32 "
                 "{%0,%1,%2,%3}, {%4,%5,%6,%7}, {%8,%9}, {%0,%1,%2,%3};"
                 : "+f"(c[0]), "+f"(c[1]), "+f"(c[2]), "+f"(c[3])
                 : "r"(a[0]), "r"(a[1]), "r"(a[2]), "r"(a[3]), "r"(b[0]), "r"(b[1]));
}
__device__ __forceinline__ void cp16(uint32_t dst, const void* src, int sz) {
    asm volatile("cp.async.cg.shared.global [%0], [%1], 16, %2;"
                 :: "r"(dst), "l"(src), "r"(sz));
}
__device__ __forceinline__ void cp_commit() {
    asm volatile("cp.async.commit_group;" ::: "memory");
}
__device__ __forceinline__ void cp_wait1() {
    asm volatile("cp.async.wait_group 1;" ::: "memory");
}
__device__ __forceinline__ void cp_wait0() {
    asm volatile("cp.async.wait_group 0;" ::: "memory");
}

// ------------------------- merged fp32 -> fp16 converter -------------------
#define NCVT 7
struct CvtArgs {
    const float4* s[NCVT];
    __half2*      h[NCVT];
    int           end[NCVT];
};

__global__ __launch_bounds__(256)
void cvt_all(CvtArgs A)
{
    int gi = blockIdx.x * 256 + threadIdx.x;
    int seg = 0;
    while (seg < NCVT && gi >= A.end[seg]) seg++;
    if (seg >= NCVT) return;
    int i = gi - (seg ? A.end[seg - 1] : 0);

    float4 v = A.s[seg][i];
    A.h[seg][2 * i]     = __half2(__float2half_rn(v.x), __float2half_rn(v.y));
    A.h[seg][2 * i + 1] = __half2(__float2half_rn(v.z), __float2half_rn(v.w));
}

// ------------------------- pipelined fp16 GEMM ------------------------------
__device__ __forceinline__ void g_load_stage(
    uint32_t sb, int slot,
    const __half* Ah, const __half* Bh,
    int bm, int bn, int kb, int M, int tid)
{
    const uint32_t abase = sb + slot * 32768;
    const uint32_t bbase = abase + 16384;
    const int c  = tid & 7;
    const int r0 = tid >> 3;
    const int kc = kb + c * 8;
#pragma unroll
    for (int ii = 0; ii < 4; ii++) {
        int r = r0 + ii * 32;
        uint32_t so = sw128((uint32_t)(r * 128 + c * 16));
        int m = bm + r;
        int mc = (m < M) ? m : (M - 1);
        cp16(abase + so, Ah + (size_t)mc * E_DIM + kc, (m < M) ? 16 : 0);
        cp16(bbase + so, Bh + (size_t)(bn + r) * E_DIM + kc, 16);
    }
}

__global__ __launch_bounds__(256, 2)
void gemm_mma(const __half* __restrict__ A0, const __half* __restrict__ A3,
              const __half* __restrict__ W,
              const float* b0, const float* b1, const float* b2, const float* b3,
              float* o0, float* o1, float* o2, float* o3,
              float s0, float s1, float s2, float s3,
              int M0, int M3, int mode, int Trows0, int Trows3)
{
    extern __shared__ char smem[];
    const uint32_t sb = smem_u32(smem);

    const int tid = threadIdx.x, wid = tid >> 5, lane = tid & 31;
    const int bm = blockIdx.y * 128, bn = blockIdx.x * 128;
    const int z = blockIdx.z;
    const int M     = (z == 3) ? M3 : M0;
    const int Trows = (z == 3) ? Trows3 : Trows0;
    if (bm >= M) return;
    const __half* Ah = (z == 3) ? A3 : A0;
    const __half* wh = W + (size_t)z * NE;
    const float* bias = (z == 0) ? b0 : ((z == 1) ? b1 : ((z == 2) ? b2 : b3));
    float* out        = (z == 0) ? o0 : ((z == 1) ? o1 : ((z == 2) ? o2 : o3));
    const float scale = (z == 0) ? s0 : ((z == 1) ? s1 : ((z == 2) ? s2 : s3));

    const int warpM = (wid >> 2) * 64;
    const int warpN = (wid & 3) * 32;
    const int li = lane >> 3, lr = lane & 7;

    float acc[4][4][4];
#pragma unroll
    for (int i = 0; i < 4; i++)
#pragma unroll
        for (int j = 0; j < 4; j++)
#pragma unroll
            for (int k = 0; k < 4; k++) acc[i][j][k] = 0.f;

    const int NK = E_DIM / 64;
    g_load_stage(sb, 0, Ah, wh, bm, bn, 0, M, tid);
    cp_commit();
    g_load_stage(sb, 1, Ah, wh, bm, bn, 64, M, tid);
    cp_commit();

    int slot = 0, next = 2;
    for (int ks = 0; ks < NK; ks++) {
        if (ks + 1 < NK) cp_wait1(); else cp_wait0();
        __syncthreads();
        if (ks + 2 < NK) {
            g_load_stage(sb, next, Ah, wh, bm, bn, (ks + 2) * 64, M, tid);
            cp_commit();
            if (++next == 3) next = 0;
        }

        const uint32_t abase = sb + slot * 32768;
        const uint32_t bbase = abase + 16384;
        if (++slot == 3) slot = 0;
#pragma unroll
        for (int kk = 0; kk < 4; kk++) {
            uint32_t bfr[2][4];
            const uint32_t kb2 = (uint32_t)(kk * 32 + (li & 1) * 16);
#pragma unroll
            for (int jn = 0; jn < 2; jn++) {
                uint32_t off = (uint32_t)((warpN + jn * 16 + (li >> 1) * 8 + lr) * 128) + kb2;
                ldsm_x4(bfr[jn], bbase + sw128(off));
            }
            const uint32_t ka = (uint32_t)(kk * 32 + (li >> 1) * 16);
#pragma unroll
            for (int i = 0; i < 4; i++) {
                uint32_t ah[4];
                uint32_t off = (uint32_t)((warpM + i * 16 + (li & 1) * 8 + lr) * 128) + ka;
                ldsm_x4(ah, abase + sw128(off));
#pragma unroll
                for (int j = 0; j < 4; j++)
                    mma16816(acc[i][j], ah, &bfr[j >> 1][(j & 1) * 2]);
            }
        }
    }

    const int g = lane >> 2, tg = lane & 3;
#pragma unroll
    for (int i = 0; i < 4; i++) {
#pragma unroll
        for (int j = 0; j < 4; j++) {
            int n0 = bn + warpN + j * 8 + tg * 2;
            float bx = bias[n0], by = bias[n0 + 1];
#pragma unroll
            for (int half = 0; half < 2; half++) {
                int m = bm + warpM + i * 16 + g + half * 8;
                if (m >= M) continue;
                float2 v;
                v.x = (acc[i][j][half * 2 + 0] + bx) * scale;
                v.y = (acc[i][j][half * 2 + 1] + by) * scale;
                if (mode == 0) {
                    *(float2*)&out[(size_t)m * E_DIM + n0] = v;
                } else {
                    int t = m >> 1, b = m & 1;
                    int h = n0 >> 6, d = n0 & 63;
                    *(float2*)&out[(size_t)((b * 16 + h) * Trows + t) * 64 + d] = v;
                }
            }
        }
    }
}

// ------------- merged pattn (softplus) + TWO 32-row local states ------------
__global__ __launch_bounds__(256, 4)
void pattn_local()
{
    const int bx = blockIdx.x, bh = blockIdx.y;
    extern __shared__ float sm[];
    float* kps = sm;                   // 64 x 65
    float* pqs = kps + 64 * 65;        // 32 x 65
    float* kvs = pqs + 32 * 65;        // 64 x 64
    float* ps  = kvs + 64 * 64;        // 64 x 32
    const size_t base = (size_t)bh * T_LEN + bx * 64;
    const int tid = threadIdx.x;

    for (int i = tid; i < 64 * 64; i += 256) {
        int s = i >> 6, d = i & 63;
        kps[s * 65 + d] = g_kp[(base + s) * 64 + d];
        kvs[i] = g_kv[(base + s) * 64 + d];
    }
    for (int i = tid; i < PLEN * 64; i += 256) {
        int p = i >> 6, d = i & 63;
        pqs[p * 65 + d] = g_pq[(size_t)bh * PLEN * D_DIM + i];
    }
    __syncthreads();

    {
        const int t  = tid >> 2;
        const int p0 = (tid & 3) * 8;
#pragma unroll
        for (int pp = 0; pp < 8; pp++) {
            int p = p0 + pp;
            float a0 = 0.f, a1 = 0.f, a2 = 0.f, a3 = 0.f;
#pragma unroll
            for (int d = 0; d < 64; d += 4) {
                a0 += kps[t * 65 + d]     * pqs[p * 65 + d];
                a1 += kps[t * 65 + d + 1] * pqs[p * 65 + d + 1];
                a2 += kps[t * 65 + d + 2] * pqs[p * 65 + d + 2];
                a3 += kps[t * 65 + d + 3] * pqs[p * 65 + d + 3];
            }
            float accv = (a0 + a1) + (a2 + a3);
            float zz = BETA * accv;
            float sp = (fmaxf(zz, 0.f) + log1pf(expf(-fabsf(zz)))) * (1.0f / BETA);
            ps[t * 32 + p] = sp;
            g_pattn[(base + t) * PLEN + p] = sp;
        }
    }
    __syncthreads();

    {
        const int d  = tid >> 2;
        const int j0 = (tid & 3) * 8;
        float acc0[8] = {0.f}, acc1[8] = {0.f};
        for (int s = 0; s < 32; s++) {
            float a = kvs[s * 64 + d];
#pragma unroll
            for (int jj = 0; jj < 8; jj++) acc0[jj] += a * ps[s * 32 + j0 + jj];
        }
        for (int s = 32; s < 64; s++) {
            float a = kvs[s * 64 + d];
#pragma unroll
            for (int jj = 0; jj < 8; jj++) acc1[jj] += a * ps[s * 32 + j0 + jj];
        }
        float* o0 = &g_S[((size_t)bh * NSC + 2 * bx)     * 2048];
        float* o1 = &g_S[((size_t)bh * NSC + 2 * bx + 1) * 2048];
#pragma unroll
        for (int jj = 0; jj < 8; jj++) {
            o0[d * 32 + j0 + jj] = acc0[jj];
            o1[d * 32 + j0 + jj] = acc1[jj];
        }
    }
}

// ------------------- exclusive prefix scan over 64 chunks ------------------
__global__ __launch_bounds__(256)
void scan_states()
{
    const int gi = blockIdx.x * 256 + threadIdx.x;
    const int bh = gi >> 11;
    const int e  = gi & 2047;
    float run = 0.f;
    float* p = &g_S[(size_t)bh * NSC * 2048 + e];
    for (int c = 0; c < NSC; c++) {
        float v = p[c * 2048];
        p[c * 2048] = run;
        run += v;
    }
}

// ------------------- fused pass1 + softmax + pass2 (3 CTAs/SM) --------------
__global__ __launch_bounds__(256, 3)
void fused_pass()
{
    const int bx = blockIdx.x, bh = blockIdx.y;
    extern __shared__ float sm[];
    float* qs  = sm;                 // 64 x 65
    float* kvs = qs  + 64 * 65;      // 64 x 64
    float* ps  = kvs + 64 * 64;      // 64 x 33
    float* ws  = ps  + 64 * 33;      // 64 x 33
    float* ss  = ws  + 64 * 33;      // 2 x 64 x 33   (pass2 reads it strided)
    const size_t base = (size_t)bh * T_LEN + bx * 64;
    const int tid = threadIdx.x;

    for (int i = tid; i < 64 * 64; i += 256) {
        int s = i >> 6, d = i & 63;
        kvs[i] = g_kv[(base + s) * 64 + d];
        qs[s * 65 + d] = g_q[(base + s) * 64 + d];
    }
    for (int i = tid; i < 64 * 32; i += 256) {
        int s = i >> 5, j = i & 31;
        ps[s * 33 + j] = g_pattn[base * 32 + i];
    }
    for (int i = tid; i < 2 * 64 * 32; i += 256) {
        int ci  = i >> 11;
        int idx = i & 2047;
        int d = idx >> 5, j = idx & 31;
        ss[ci * (64 * 33) + d * 33 + j] = g_S[((size_t)bh * NSC + 2 * bx + ci) * 2048 + idx];
    }
    __syncthreads();

    const int cid = tid >> 7;
    const int lt  = (tid >> 2) & 31;
    const int sub = tid & 3;
    const int row = cid * 32 + lt;
    const int tgl = bx * 64 + row;
    const float inv = 1.0f / (float)(tgl + 1);
    const int smax = lt | 7;
    const float* ssb = ss + cid * (64 * 33);
    const int srow0 = cid * 32;

    // ---------------- pass 1 ----------------
    {
        const int j0  = sub * 8;
        const int dq0 = sub * 16;
        float qreg[16];
#pragma unroll
        for (int d = 0; d < 16; d++) qreg[d] = qs[row * 65 + dq0 + d];

        float r[8];
#pragma unroll
        for (int jj = 0; jj < 8; jj++) r[jj] = 0.f;

        const float* qrow = &qs[row * 65];
#pragma unroll 8
        for (int d = 0; d < 64; d++) {
            float a = qrow[d];
#pragma unroll
            for (int jj = 0; jj < 8; jj++) r[jj] += a * ssb[d * 33 + j0 + jj];
        }
        for (int s = 0; s <= smax; s++) {
            const float* kr = &kvs[(srow0 + s) * 64 + dq0];
            float a0 = 0.f, a1 = 0.f, a2 = 0.f, a3 = 0.f;
#pragma unroll
            for (int d = 0; d < 16; d += 4) {
                a0 += qreg[d]     * kr[d];
                a1 += qreg[d + 1] * kr[d + 1];
                a2 += qreg[d + 2] * kr[d + 2];
                a3 += qreg[d + 3] * kr[d + 3];
            }
            float a = (a0 + a1) + (a2 + a3);
            a += __shfl_xor_sync(0xffffffffu, a, 1);
            a += __shfl_xor_sync(0xffffffffu, a, 2);
            if (s <= lt) {
                const float* pr = &ps[(srow0 + s) * 33 + j0];
#pragma unroll
                for (int jj = 0; jj < 8; jj++) r[jj] += a * pr[jj];
            }
        }
        float mx = -1e30f;
#pragma unroll
        for (int jj = 0; jj < 8; jj++) { r[jj] *= inv; mx = fmaxf(mx, r[jj]); }
        mx = fmaxf(mx, __shfl_xor_sync(0xffffffffu, mx, 1));
        mx = fmaxf(mx, __shfl_xor_sync(0xffffffffu, mx, 2));
        float sum = 0.f;
#pragma unroll
        for (int jj = 0; jj < 8; jj++) { r[jj] = expf(r[jj] - mx); sum += r[jj]; }
        sum += __shfl_xor_sync(0xffffffffu, sum, 1);
        sum += __shfl_xor_sync(0xffffffffu, sum, 2);
        float rs = 1.0f / sum;
#pragma unroll
        for (int jj = 0; jj < 8; jj++) ws[row * 33 + j0 + jj] = r[jj] * rs;
    }
    __syncwarp();

    // ---------------- pass 2 ----------------
    {
        const int d0 = sub * 16;
        const int jw0 = sub * 8;
        float wreg[32];
#pragma unroll
        for (int j = 0; j < 32; j++) wreg[j] = ws[row * 33 + j];

        float r[16];
#pragma unroll
        for (int dd = 0; dd < 16; dd++) r[dd] = 0.f;

        // inter-chunk: w[t] @ S^T_prefix, reading ss[(d)(33)+j] strided
#pragma unroll 8
        for (int j = 0; j < 32; j++) {
            float a = wreg[j];
            const float* sc = &ssb[d0 * 33 + j];
#pragma unroll
            for (int dd = 0; dd < 16; dd++) r[dd] += a * sc[dd * 33];
        }
        for (int s = 0; s <= smax; s++) {
            const float* pr = &ps[(srow0 + s) * 33 + jw0];
            float a0 = 0.f, a1 = 0.f;
#pragma unroll
            for (int j = 0; j < 8; j += 2) {
                a0 += wreg[jw0 + j]     * pr[j];
                a1 += wreg[jw0 + j + 1] * pr[j + 1];
            }
            float a = a0 + a1;
            a += __shfl_xor_sync(0xffffffffu, a, 1);
            a += __shfl_xor_sync(0xffffffffu, a, 2);
            if (s <= lt) {
                const float* kr = &kvs[(srow0 + s) * 64 + d0];
#pragma unroll
                for (int dd = 0; dd < 16; dd++) r[dd] += a * kr[dd];
            }
        }
        const int b = bh >> 4, hh = bh & 15;
        const size_t ob = ((size_t)tgl * 2 + b) * 1024 + hh * 64 + d0;
#pragma unroll
        for (int dd = 0; dd < 16; dd++)
            g_ATh[ob + dd] = __float2half_rn(r[dd] * inv);
    }
}

// ---------------------------------------------------------------------------
extern "C" void kernel_launch(void* const* d_in, const int* in_sizes, int n_in,
                              void* d_out, int out_size)
{
    const float* query  = (const float*)d_in[0];
    const float* pquery = (const float*)d_in[1];
    const float* Wpq = (const float*)d_in[2];
    const float* bpq = (const float*)d_in[3];
    const float* Wq  = (const float*)d_in[4];
    const float* bq  = (const float*)d_in[5];
    const float* Wpc = (const float*)d_in[6];
    const float* bpc = (const float*)d_in[7];
    const float* Wc  = (const float*)d_in[8];
    const float* bc  = (const float*)d_in[9];
    const float* Wo  = (const float*)d_in[10];
    const float* bo  = (const float*)d_in[11];
    float* out = (float*)d_out;

    float *p_pq, *p_q, *p_kp, *p_kv;
    __half *p_Ah, *p_PQh, *p_W4h, *p_WOh, *p_ATh;
    cudaGetSymbolAddress((void**)&p_pq,  g_pq);
    cudaGetSymbolAddress((void**)&p_q,   g_q);
    cudaGetSymbolAddress((void**)&p_kp,  g_kp);
    cudaGetSymbolAddress((void**)&p_kv,  g_kv);
    cudaGetSymbolAddress((void**)&p_Ah,  g_Ah);
    cudaGetSymbolAddress((void**)&p_PQh, g_PQh);
    cudaGetSymbolAddress((void**)&p_W4h, g_W4h);
    cudaGetSymbolAddress((void**)&p_WOh, g_WOh);
    cudaGetSymbolAddress((void**)&p_ATh, g_ATh);

    const int GEMM_SMEM = 3 * 32768;
    const int PL_SMEM = (64 * 65 + 32 * 65 + 64 * 64 + 64 * 32) * 4;                 // 49536
    const int FP_SMEM = (64 * 65 + 64 * 64 + 64 * 33 + 64 * 33 + 2 * 64 * 33) * 4;  // 66816
    cudaFuncSetAttribute(gemm_mma,    cudaFuncAttributeMaxDynamicSharedMemorySize, GEMM_SMEM);
    cudaFuncSetAttribute(pattn_local, cudaFuncAttributeMaxDynamicSharedMemorySize, PL_SMEM);
    cudaFuncSetAttribute(fused_pass,  cudaFuncAttributeMaxDynamicSharedMemorySize, FP_SMEM);

    // ---- launch 0: ALL conversions ----
    CvtArgs ca;
    int acc = 0, n4;
    n4 = MROWS * E_DIM / 4;
    ca.s[0] = (const float4*)query;  ca.h[0] = (__half2*)p_Ah;  acc += n4; ca.end[0] = acc;
    n4 = 64 * E_DIM / 4;
    ca.s[1] = (const float4*)pquery; ca.h[1] = (__half2*)p_PQh; acc += n4; ca.end[1] = acc;
    n4 = NE / 4;
    ca.s[2] = (const float4*)Wq;  ca.h[2] = (__half2*)p_W4h;            acc += n4; ca.end[2] = acc;
    ca.s[3] = (const float4*)Wpc; ca.h[3] = (__half2*)(p_W4h + NE);     acc += n4; ca.end[3] = acc;
    ca.s[4] = (const float4*)Wc;  ca.h[4] = (__half2*)(p_W4h + 2 * NE); acc += n4; ca.end[4] = acc;
    ca.s[5] = (const float4*)Wpq; ca.h[5] = (__half2*)(p_W4h + 3 * NE); acc += n4; ca.end[5] = acc;
    ca.s[6] = (const float4*)Wo;  ca.h[6] = (__half2*)p_WOh;            acc += n4; ca.end[6] = acc;
    cvt_all<<<(acc + 255) / 256, 256>>>(ca);

    // ---- launch 1: q/kp/kv/pq projections (z = 0..3) ----
    gemm_mma<<<dim3(8, 32, 4), 256, GEMM_SMEM>>>(
        p_Ah, p_PQh, p_W4h,
        bq, bpc, bc, bpq,
        p_q, p_kp, p_kv, p_pq,
        SCALING, 1.0f, 1.0f, SCALING,
        MROWS, 64, 1, T_LEN, PLEN);

    // ---- launch 2: pattn + two 32-row local states per block ----
    pattn_local<<<dim3(T_LEN / 64, BH), 256, PL_SMEM>>>();

    // ---- launch 3: exclusive scan over 64 chunks ----
    scan_states<<<BH * 2048 / 256, 256>>>();

    // ---- launch 4: fused pass1 + softmax + pass2 ----
    fused_pass<<<dim3(T_LEN / 64, BH), 256, FP_SMEM>>>();

    // ---- launch 5: output projection -> d_out ----
    gemm_mma<<<dim3(8, 32, 1), 256, GEMM_SMEM>>>(
        p_ATh, p_ATh, p_WOh,
        bo, bo, bo, bo,
        out, out, out, out,
        1.0f, 1.0f, 1.0f, 1.0f,
        MROWS, MROWS, 0, 0, 0);
}